// round 1
// baseline (speedup 1.0000x reference)
#include <cuda_runtime.h>
#include <math.h>

// Problem constants
#define BATCH 16
#define HH 512
#define WW 512
#define WIN 15
#define RAD 7          // WIN/2
// Tile configuration: each CTA computes a 64x64 output tile.
#define OTR 64
#define OTC 64
#define ITR (OTR + WIN - 1)   // 78 input rows
#define ITC (OTC + WIN - 1)   // 78 input cols
#define SP  79                // smem pitch for raw input tiles (odd -> conflict-free column walks)
#define HP  65                // smem pitch for moment planes
#define NTHREADS 512

#define SI_ELEMS (ITR * SP)                       // 6162 floats per raw plane
#define SMEM_BYTES (2 * SI_ELEMS * 4 /* sI,sJ */ \
                  + ITR * HP * 16   /* hA float4 */ \
                  + ITR * HP * 4)   /* hB float  */
// = 49296 + 81120 + 20280 = 150696 bytes

// Global scratch for the reduction: [cross, I_var, J_var]
__device__ double g_acc[3];

__global__ void ncc_zero_kernel() {
    g_acc[0] = 0.0; g_acc[1] = 0.0; g_acc[2] = 0.0;
}

extern __shared__ float smem[];

__global__ void __launch_bounds__(NTHREADS, 1)
ncc_main_kernel(const float* __restrict__ I, const float* __restrict__ J) {
    float*  sI = smem;
    float*  sJ = smem + SI_ELEMS;
    float4* hA = (float4*)(smem + 2 * SI_ELEMS);  // (I,J,II,JJ) horizontal sums; 2*SI_ELEMS*4 % 16 == 0
    float*  hB = (float*)(hA + ITR * HP);         // IJ horizontal sums

    const int tid = threadIdx.x;
    const int b   = blockIdx.z;
    const int gy0 = blockIdx.y * OTR - RAD;
    const int gx0 = blockIdx.x * OTC - RAD;
    const float* __restrict__ Ib = I + (size_t)b * HH * WW;
    const float* __restrict__ Jb = J + (size_t)b * HH * WW;

    // ---- Phase A: load 78x78 halo tile of I and J (zero padding outside) ----
    for (int idx = tid; idx < ITR * ITC; idx += NTHREADS) {
        int ty = idx / ITC;
        int tx = idx - ty * ITC;
        int gy = gy0 + ty;
        int gx = gx0 + tx;
        float vi = 0.0f, vj = 0.0f;
        if (gy >= 0 && gy < HH && gx >= 0 && gx < WW) {
            int g = gy * WW + gx;
            vi = Ib[g];
            vj = Jb[g];
        }
        sI[ty * SP + tx] = vi;
        sJ[ty * SP + tx] = vj;
    }
    __syncthreads();

    // ---- Phase B: horizontal 15-tap sliding sums for 5 moments, all 78 rows ----
    // thread layout: ty = tid>>1 (0..77), cg = tid&1 -> columns [cg*32, cg*32+32)
    if (tid < 2 * ITR) {
        const int ty = tid >> 1;
        const int cg = tid & 1;
        const int x0 = cg * 32;
        const float* rI = sI + ty * SP;
        const float* rJ = sJ + ty * SP;

        float aI = 0.f, aJ = 0.f, aII = 0.f, aJJ = 0.f, aIJ = 0.f;
        #pragma unroll
        for (int k = 0; k < WIN; k++) {
            float vi = rI[x0 + k];
            float vj = rJ[x0 + k];
            aI  += vi;       aJ  += vj;
            aII += vi * vi;  aJJ += vj * vj;
            aIJ += vi * vj;
        }
        #pragma unroll 4
        for (int i = 0; i < 32; i++) {
            const int x = x0 + i;
            hA[ty * HP + x] = make_float4(aI, aJ, aII, aJJ);
            hB[ty * HP + x] = aIJ;
            if (i < 31) {
                float ni = rI[x + WIN], nj = rJ[x + WIN];
                float oi = rI[x],       oj = rJ[x];
                aI  += ni - oi;
                aJ  += nj - oj;
                aII += ni * ni - oi * oi;
                aJJ += nj * nj - oj * oj;
                aIJ += ni * nj - oi * oj;
            }
        }
    }
    __syncthreads();

    // ---- Phase C: vertical 15-tap sliding sums + per-pixel combine + accumulate ----
    // thread layout: tx = tid&63 (output col), rg = tid>>6 (0..7) -> output rows [rg*8, rg*8+8)
    const int tx    = tid & 63;
    const int rg    = tid >> 6;
    const int rbase = rg * 8;

    float4 a4 = make_float4(0.f, 0.f, 0.f, 0.f);
    float  aB = 0.f;
    #pragma unroll
    for (int k = 0; k < WIN; k++) {
        float4 v = hA[(rbase + k) * HP + tx];
        a4.x += v.x; a4.y += v.y; a4.z += v.z; a4.w += v.w;
        aB   += hB[(rbase + k) * HP + tx];
    }

    const float inv = 1.0f / 225.0f;
    float c_cross = 0.f, c_iv = 0.f, c_jv = 0.f;
    #pragma unroll
    for (int i = 0; i < 8; i++) {
        float SI = a4.x, SJ = a4.y;
        c_cross += aB   - SI * SJ * inv;
        c_iv    += a4.z - SI * SI * inv;
        c_jv    += a4.w - SJ * SJ * inv;
        if (i < 7) {
            float4 vn = hA[(rbase + i + WIN) * HP + tx];
            float4 vo = hA[(rbase + i) * HP + tx];
            a4.x += vn.x - vo.x;
            a4.y += vn.y - vo.y;
            a4.z += vn.z - vo.z;
            a4.w += vn.w - vo.w;
            aB   += hB[(rbase + i + WIN) * HP + tx] - hB[(rbase + i) * HP + tx];
        }
    }

    // ---- Reduction: warp shuffle -> smem -> one double atomicAdd triple per block ----
    #pragma unroll
    for (int off = 16; off > 0; off >>= 1) {
        c_cross += __shfl_xor_sync(0xFFFFFFFFu, c_cross, off);
        c_iv    += __shfl_xor_sync(0xFFFFFFFFu, c_iv, off);
        c_jv    += __shfl_xor_sync(0xFFFFFFFFu, c_jv, off);
    }
    const int lane = tid & 31;
    const int warp = tid >> 5;
    float* red = smem;  // reuse sI region (nobody reads sI in phase C)
    if (lane == 0) {
        red[warp]      = c_cross;
        red[16 + warp] = c_iv;
        red[32 + warp] = c_jv;
    }
    __syncthreads();
    if (tid == 0) {
        double s0 = 0.0, s1 = 0.0, s2 = 0.0;
        #pragma unroll
        for (int w = 0; w < NTHREADS / 32; w++) {
            s0 += (double)red[w];
            s1 += (double)red[16 + w];
            s2 += (double)red[32 + w];
        }
        atomicAdd(&g_acc[0], s0);
        atomicAdd(&g_acc[1], s1);
        atomicAdd(&g_acc[2], s2);
    }
}

__global__ void ncc_finalize_kernel(float* __restrict__ out) {
    double cc = g_acc[0] / sqrt(g_acc[1] * g_acc[2]);
    out[0] = (float)(-cc);
}

extern "C" void kernel_launch(void* const* d_in, const int* in_sizes, int n_in,
                              void* d_out, int out_size) {
    const float* I = (const float*)d_in[0];
    const float* J = (const float*)d_in[1];
    float* out = (float*)d_out;

    cudaFuncSetAttribute(ncc_main_kernel,
                         cudaFuncAttributeMaxDynamicSharedMemorySize, SMEM_BYTES);

    ncc_zero_kernel<<<1, 1>>>();
    dim3 grid(WW / OTC, HH / OTR, BATCH);  // (8, 8, 16) = 1024 CTAs
    ncc_main_kernel<<<grid, NTHREADS, SMEM_BYTES>>>(I, J);
    ncc_finalize_kernel<<<1, 1>>>(out);
}